// round 17
// baseline (speedup 1.0000x reference)
#include <cuda_runtime.h>
#include <cstdint>
#include <cstddef>

#define NPT 262144
#define C0  262144
#define FULLM 0xffffffffu
typedef unsigned long long ull;

__constant__ int cNX[27] = {-1,0,1,-1,0,1,-1,0,1,-1,0,1,-1,0,1,-1,0,1,-1,0,1,-1,0,1,-1,0,1};
__constant__ int cNY[27] = {-1,-1,-1,0,0,0,1,1,1,-1,-1,-1,0,0,0,1,1,1,-1,-1,-1,0,0,0,1,1,1};
__constant__ int cNZ[27] = {-1,-1,-1,-1,-1,-1,-1,-1,-1,0,0,0,0,0,0,0,0,0,1,1,1,1,1,1,1,1,1};

struct __align__(256) GG {
    // ---------- zero block (memset each launch) ----------
    int   occ0[C0];
    int   cnt0[C0];
    int   cur0[C0];
    int   occL[32768];
    int   cntL[32768];
    int   curL[32768];
    float svraw[299584 * 10];
    int   tick[16];
    ull   scanflags[2304];
    int   tot[16];          // 0..4 = n_l, 5 = T, 6 = E
    int   zend[4];
    // ---------- rest ----------
    int   cid[NPT];
    int   rank0[C0];
    int   cstart0[C0];
    int   order0[NPT];
    int   seg0[NPT];
    int   pdeg[NPT];
    int   poff[NPT];
    int   neA[299584];
    int   rankL[32768];
    int   cstartL[32768];
    int   segL[299520];
    int   ordL[299520];
    int   bmask[216];
    int   Stab[3 * 128 * 6];
    int   Ttab[3 * 128 * 6];
    int   mnb[4], mxb[4];
    float bnd[3 * 63];
    int oassign, osv, oedge, oids, A, S, E;
    int svb[5], ab[5];
};
__device__ GG g;

__device__ __align__(16) int g_rinfo0[C0];
__device__ __align__(16) int g_rinfoL[37440];
__device__ __align__(16) int g_ecnt8[8088768];
__device__ __align__(16) int g_eoff8[8088768];

// ------------------------------------------------------------------ scan utils
__device__ __forceinline__ int wscan(int x) {
    int lane = threadIdx.x & 31;
#pragma unroll
    for (int d = 1; d < 32; d <<= 1) {
        int y = __shfl_up_sync(FULLM, x, d);
        if (lane >= d) x += y;
    }
    return x;
}
__device__ __forceinline__ ull wscan64(ull x) {
    int lane = threadIdx.x & 31;
#pragma unroll
    for (int d = 1; d < 32; d <<= 1) {
        ull y = __shfl_up_sync(FULLM, x, d);
        if (lane >= d) x += y;
    }
    return x;
}

// single-array scan: 512 thr x 16 items, warp-parallel lookback
__global__ void __launch_bounds__(512) k_scan1(const int* __restrict__ in, int* __restrict__ out,
                                               int n, int* tot, int ti, int fo) {
    __shared__ int sbid, sexc;
    __shared__ int wsum[16], woff[16];
    int tid = threadIdx.x;
    if (tid == 0) sbid = atomicAdd(&g.tick[ti], 1);
    __syncthreads();
    int bid = sbid;
    int base = bid * 8192 + tid * 16;
    int v[16]; int t = 0;
    if (base + 16 <= n) {
        const int4* p = (const int4*)(in + base);
#pragma unroll
        for (int j = 0; j < 4; j++) {
            int4 x = __ldg(p + j);
            v[4*j] = x.x; v[4*j+1] = x.y; v[4*j+2] = x.z; v[4*j+3] = x.w;
        }
    } else {
#pragma unroll
        for (int j = 0; j < 16; j++) v[j] = (base + j < n) ? in[base + j] : 0;
    }
#pragma unroll
    for (int j = 0; j < 16; j++) t += v[j];
    int inc = wscan(t);
    if ((tid & 31) == 31) wsum[tid >> 5] = inc;
    __syncthreads();
    if (tid < 32) {
        int x = (tid < 16) ? wsum[tid] : 0;
        int iw = wscan(x);
        if (tid < 16) woff[tid] = iw - x;
        int B = __shfl_sync(FULLM, iw, 15);
        ull* fl = g.scanflags + fo;
        int exc = 0;
        if (bid == 0) {
            if (tid == 0) atomicExch(&fl[0], (2ULL << 62) | (unsigned)B);
        } else {
            if (tid == 0) atomicExch(&fl[bid], (1ULL << 62) | (unsigned)B);
            int lb = bid - 1;
            while (true) {
                int idx = lb - tid;
                ull w = 0; int st = 2;
                if (idx >= 0) {
                    do { w = atomicAdd(&fl[idx], 0ULL); } while (!(w >> 62));
                    st = (int)(w >> 62);
                }
                unsigned pm = __ballot_sync(FULLM, st == 2);
                int val = (int)(unsigned)w;
                int firstP = pm ? (__ffs(pm) - 1) : 32;
                if (tid > firstP) val = 0;
#pragma unroll
                for (int d = 16; d >= 1; d >>= 1) val += __shfl_xor_sync(FULLM, val, d);
                exc += val;
                if (pm) break;
                lb -= 32;
            }
            if (tid == 0) atomicExch(&fl[bid], (2ULL << 62) | (unsigned)(exc + B));
        }
        if (tid == 0) { sexc = exc; if (tot && bid == (int)gridDim.x - 1) *tot = exc + B; }
    }
    __syncthreads();
    int off = sexc + woff[tid >> 5] + inc - t;
    if (base + 16 <= n) {
        int4* q = (int4*)(out + base);
#pragma unroll
        for (int j = 0; j < 4; j++) {
            int4 x;
            x.x = off; off += v[4*j];
            x.y = off; off += v[4*j+1];
            x.z = off; off += v[4*j+2];
            x.w = off; off += v[4*j+3];
            q[j] = x;
        }
    } else {
        for (int j = 0; j < 16; j++) { if (base + j < n) out[base + j] = off; off += v[j]; }
    }
}

// dual-array scan (packed 28-bit fields)
#define M28 ((1ULL << 28) - 1)
__global__ void __launch_bounds__(512) k_scan2(const int* __restrict__ in1, const int* __restrict__ in2,
                                               int* __restrict__ out1, int* __restrict__ out2,
                                               int n, int* tot1, int ti, int fo) {
    __shared__ int sbid;
    __shared__ ull sexc2;
    __shared__ ull wsum[16], woff[16];
    int tid = threadIdx.x;
    if (tid == 0) sbid = atomicAdd(&g.tick[ti], 1);
    __syncthreads();
    int bid = sbid;
    int base = bid * 8192 + tid * 16;
    ull v[16]; ull t = 0;
#pragma unroll
    for (int j = 0; j < 16; j++) {
        ull x = 0;
        if (base + j < n) x = (ull)(unsigned)in1[base + j] | ((ull)(unsigned)in2[base + j] << 28);
        v[j] = x; t += x;
    }
    ull inc = wscan64(t);
    if ((tid & 31) == 31) wsum[tid >> 5] = inc;
    __syncthreads();
    if (tid < 32) {
        ull x = (tid < 16) ? wsum[tid] : 0;
        ull iw = wscan64(x);
        if (tid < 16) woff[tid] = iw - x;
        ull B = __shfl_sync(FULLM, iw, 15);
        ull* fl = g.scanflags + fo;
        ull exc = 0;
        if (bid == 0) {
            if (tid == 0) atomicExch(&fl[0], (2ULL << 62) | B);
        } else {
            if (tid == 0) atomicExch(&fl[bid], (1ULL << 62) | B);
            int lb = bid - 1;
            while (true) {
                int idx = lb - tid;
                ull w = 0; int st = 2;
                if (idx >= 0) {
                    do { w = atomicAdd(&fl[idx], 0ULL); } while (!(w >> 62));
                    st = (int)(w >> 62);
                }
                unsigned pm = __ballot_sync(FULLM, st == 2);
                ull val = w & ((1ULL << 56) - 1);
                int firstP = pm ? (__ffs(pm) - 1) : 32;
                if (tid > firstP) val = 0;
#pragma unroll
                for (int d = 16; d >= 1; d >>= 1) val += __shfl_xor_sync(FULLM, val, d);
                exc += val;
                if (pm) break;
                lb -= 32;
            }
            if (tid == 0) atomicExch(&fl[bid], (2ULL << 62) | (exc + B));
        }
        if (tid == 0) { sexc2 = exc; if (tot1 && bid == (int)gridDim.x - 1) *tot1 = (int)((exc + B) & M28); }
    }
    __syncthreads();
    ull off = sexc2 + woff[tid >> 5] + inc - t;
#pragma unroll
    for (int j = 0; j < 16; j++) {
        if (base + j < n) { out1[base + j] = (int)(off & M28); out2[base + j] = (int)((off >> 28) & M28); }
        off += v[j];
    }
}

// ------------------------------------------------------------------ stage A
__global__ void k_init2() {
    int t = threadIdx.x;
    if (t < 3) { g.mnb[t] = 0x7f7fffff; g.mxb[t] = 0; }
    if (t < 216) {
        int k = t >> 3, a = t & 7;
        int ox = cNX[k], oy = cNY[k], oz = cNZ[k];
        int ax = a & 1, ay = (a >> 1) & 1, az = a >> 2;
        int m = 0;
        for (int b = 0; b < 8; b++) {
            int dx = 2 * ox + (b & 1) - ax;
            int dy = 2 * oy + ((b >> 1) & 1) - ay;
            int dz = 2 * oz + (b >> 2) - az;
            if (dx > 1 || dx < -1 || dy > 1 || dy < -1 || dz > 1 || dz < -1) m |= 1 << b;
        }
        g.bmask[t] = m;
    }
}

__global__ void __launch_bounds__(256) k_foldpre(const float* __restrict__ nodes) {
    int blk = blockIdx.x;             // 768 = c*6 + kk
    int c = blk / 6, kk = blk % 6, kb = kk + 12;
    float scale = __int_as_float((23 - kb + 127) << 23);
    int t = threadIdx.x;
    int s0 = 0, s1 = 0, s2 = 0, tie = 0;
    for (int e = t; e < 2048; e += 256) {
        const float* p = nodes + ((size_t)c * 2048 + e) * 10 + 4;
        float v0 = __fmul_rn(__ldg(p + 0), scale);
        float v1 = __fmul_rn(__ldg(p + 1), scale);
        float v2 = __fmul_rn(__ldg(p + 2), scale);
        int q0 = __float2int_rn(v0), q1 = __float2int_rn(v1), q2 = __float2int_rn(v2);
        if (fabsf(__fsub_rn(v0, (float)q0)) == 0.5f) tie = 1;
        if (fabsf(__fsub_rn(v1, (float)q1)) == 0.5f) tie = 1;
        if (fabsf(__fsub_rn(v2, (float)q2)) == 0.5f) tie = 1;
        s0 += q0; s1 += q1; s2 += q2;
    }
    s0 = __reduce_add_sync(FULLM, s0);
    s1 = __reduce_add_sync(FULLM, s1);
    s2 = __reduce_add_sync(FULLM, s2);
    tie = __any_sync(FULLM, tie);
    __shared__ int sh[8][4];
    int wid = t >> 5;
    if ((t & 31) == 0) { sh[wid][0] = s0; sh[wid][1] = s1; sh[wid][2] = s2; sh[wid][3] = tie; }
    __syncthreads();
    if (t == 0) {
        int a0 = 0, a1 = 0, a2 = 0, tt = 0;
        for (int w = 0; w < 8; w++) { a0 += sh[w][0]; a1 += sh[w][1]; a2 += sh[w][2]; tt |= sh[w][3]; }
        g.Stab[(0 * 128 + c) * 6 + kk] = a0;
        g.Stab[(1 * 128 + c) * 6 + kk] = a1;
        g.Stab[(2 * 128 + c) * 6 + kk] = a2;
        g.Ttab[(0 * 128 + c) * 6 + kk] = tt;
        g.Ttab[(1 * 128 + c) * 6 + kk] = tt;
        g.Ttab[(2 * 128 + c) * 6 + kk] = tt;
    }
}

__global__ void k_mmx(const float* __restrict__ nodes) {
    int t = blockIdx.x * blockDim.x + threadIdx.x;
    int i0 = t * 64;
    if (i0 >= NPT) return;
    int mn[3] = {0x7f7fffff, 0x7f7fffff, 0x7f7fffff};
    int mx[3] = {0, 0, 0};
    for (int i = i0; i < i0 + 64; i++) {
#pragma unroll
        for (int d = 0; d < 3; d++) {
            int b = __float_as_int(nodes[i * 10 + 4 + d]);
            mn[d] = min(mn[d], b);
            mx[d] = max(mx[d], b);
        }
    }
#pragma unroll
    for (int d = 0; d < 3; d++) {
        atomicMin(&g.mnb[d], mn[d]);
        atomicMax(&g.mxb[d], mx[d]);
    }
}

__global__ void k_fold3b(const float* __restrict__ nodes) {
    __shared__ float sref[3];
    int tid = threadIdx.x;
    if ((tid & 31) == 0 && tid < 96) {
        int d = tid >> 5;
        float s = 0.f;
        for (int c = 0; c < 128; c++) {
            int kb = (__float_as_int(s) >> 23) - 127;
            bool ok = false;
            float cand = 0.f;
            if (s > 0.f && kb >= 12 && kb <= 17) {
                int idx = (d * 128 + c) * 6 + (kb - 12);
                int S = g.Stab[idx];
                int tie = g.Ttab[idx];
                float u = __int_as_float((kb - 23 + 127) << 23);
                cand = __fadd_rn(s, __fmul_rn((float)S, u));
                float lim = __int_as_float((kb + 1 + 127) << 23);
                if (!tie && __fadd_rn(cand, 4.0f) < lim) ok = true;
            }
            if (ok) {
                s = cand;
            } else {
                const float* p = nodes + (size_t)c * 2048 * 10 + 4 + d;
#pragma unroll 8
                for (int e = 0; e < 2048; e++)
                    s = __fadd_rn(s, __ldg(p + e * 10));
            }
        }
        sref[d] = s * (1.0f / 262144.0f);
    }
    __syncthreads();
    float d0 = __fsub_rn(__int_as_float(g.mxb[0]), __int_as_float(g.mnb[0]));
    float d1 = __fsub_rn(__int_as_float(g.mxb[1]), __int_as_float(g.mnb[1]));
    float d2 = __fsub_rn(__int_as_float(g.mxb[2]), __int_as_float(g.mnb[2]));
    float box = fmaxf(d0, fmaxf(d1, d2));
    double half = (double)box * 0.5;
    float hf = (float)half;
    for (int t = tid; t < 189; t += 128) {
        int d = t / 63, i = t % 63 + 1;
        float r = sref[d];
        float start = __fsub_rn(r, hf);
        float stop  = __fadd_rn(r, hf);
        float delta = __fsub_rn(stop, start);
        float step  = __fmul_rn(delta, 1.0f / 64.0f);
        float b = __fadd_rn(__fmul_rn((float)i, step), start);
        g.bnd[d * 63 + (i - 1)] = b;
    }
}

__device__ __forceinline__ int ub63(const float* __restrict__ b, float v) {
    int lo = 0, hi = 63;
    while (lo < hi) {
        int m = (lo + hi) >> 1;
        if (b[m] <= v) lo = m + 1; else hi = m;
    }
    return lo;
}

__global__ void k_cells(const float* __restrict__ nodes) {
    int i = blockIdx.x * blockDim.x + threadIdx.x;
    if (i >= NPT) return;
    float x = nodes[i * 10 + 4], y = nodes[i * 10 + 5], z = nodes[i * 10 + 6];
    int xg = ub63(g.bnd, x);
    int yg = 63 - ub63(g.bnd + 63, y);
    int zg = 63 - ub63(g.bnd + 126, z);
    int c = xg + (yg << 6) + (zg << 12);
    g.cid[i] = c;
    g.occ0[c] = 1;
    atomicAdd(&g.cnt0[c], 1);
}

__global__ void k_post0() {
    int c = blockIdx.x * blockDim.x + threadIdx.x;
    if (c >= C0) return;
    int o = g.occ0[c];
    int r = g.rank0[c];
    g_rinfo0[c] = o ? r + 1 : 0;
    if (o) g.neA[r] = c;
}

// separable 3x3x3 box filter over the 64^3 cell grid (exact integer sums)
__global__ void k_conv(const int* __restrict__ in, int* __restrict__ outp, int shift) {
    int c = blockIdx.x * blockDim.x + threadIdx.x;
    if (c >= C0) return;
    int coord = (c >> shift) & 63;
    int stride = 1 << shift;
    int s = in[c];
    if (coord > 0) s += in[c - stride];
    if (coord < 63) s += in[c + stride];
    outp[c] = s;
}

__global__ void k_scatseg(const int* __restrict__ degc) {
    int i = blockIdx.x * blockDim.x + threadIdx.x;
    if (i >= NPT) return;
    int c = g.cid[i];
    int slot = g.cstart0[c] + atomicAdd(&g.cur0[c], 1);
    g.order0[slot] = i;
    g.seg0[i] = g.rank0[c];
    g.pdeg[i] = degc[c];
}

// register-staged insertion sort (runs are tiny; global fallback for safety)
__global__ void k_sort0() {
    int c = blockIdx.x * blockDim.x + threadIdx.x;
    if (c >= C0) return;
    int n = g.cnt0[c];
    if (n < 2) return;
    int* a = g.order0 + g.cstart0[c];
    if (n <= 32) {
        int buf[32];
        for (int i = 0; i < n; i++) buf[i] = a[i];
        for (int i = 1; i < n; i++) {
            int v = buf[i], j = i - 1;
            while (j >= 0 && buf[j] > v) { buf[j + 1] = buf[j]; j--; }
            buf[j + 1] = v;
        }
        for (int i = 0; i < n; i++) a[i] = buf[i];
    } else {
        for (int i = 1; i < n; i++) {
            int v = a[i], j = i - 1;
            while (j >= 0 && a[j] > v) { a[j + 1] = a[j]; j--; }
            a[j + 1] = v;
        }
    }
}

// two-phase graph write: prefetch all 27 (cnt,cstart) pairs, then write runs
__global__ void __launch_bounds__(256) k_gwrite(float* __restrict__ out) {
    int i = blockIdx.x * blockDim.x + threadIdx.x;
    if (i >= NPT) return;
    int T = g.tot[5];
    int c = g.cid[i];
    int x = c & 63, y = (c >> 6) & 63, z = c >> 12;
    int nn[27], bs[27];
#pragma unroll
    for (int k = 0; k < 27; k++) {
        int nx = x + cNX[k], ny = y + cNY[k], nz = z + cNZ[k];
        bool valid = (unsigned)nx < 64u && (unsigned)ny < 64u && (unsigned)nz < 64u;
        int cc = valid ? (nx + (ny << 6) + (nz << 12)) : 0;
        nn[k] = valid ? g.cnt0[cc] : 0;
        bs[k] = valid ? g.cstart0[cc] : 0;
    }
    int col = g.poff[i];
    float fi = (float)i;
#pragma unroll
    for (int k = 0; k < 27; k++) {
        int n = nn[k], b = bs[k];
        for (int t = 0; t < n; t++) {
            out[col] = (float)g.order0[b + t];
            out[T + col] = fi;
            col++;
        }
    }
}

// ------------------------------------------------------------------ level 1 (64->32)
__global__ void k_l1occup() {
    int r = blockIdx.x * blockDim.x + threadIdx.x;
    if (r >= g.tot[0]) return;
    int e = g.neA[r];
    g.occL[((e & 63) >> 1) | ((((e >> 6) & 63) >> 1) << 5) | (((e >> 12) >> 1) << 10)] = 1;
}

__global__ void k_l1post() {
    int c = blockIdx.x * blockDim.x + threadIdx.x;
    if (c >= 32768) return;
    int o = g.occL[c];
    int r = g.rankL[c];
    g_rinfoL[c] = o ? r + 1 : 0;
    if (o) g.neA[262144 + r] = c;
}

__global__ void k_l1seg() {
    int r = blockIdx.x * blockDim.x + threadIdx.x;
    if (r >= g.tot[0]) return;
    int e = g.neA[r];
    int s = g.rankL[((e & 63) >> 1) | ((((e >> 6) & 63) >> 1) << 5) | (((e >> 12) >> 1) << 10)];
    g.segL[r] = s;
    atomicAdd(&g.cntL[s], 1);
}

__global__ void k_l1scat() {
    int r = blockIdx.x * blockDim.x + threadIdx.x;
    if (r >= g.tot[0]) return;
    int s = g.segL[r];
    g.ordL[g.cstartL[s] + atomicAdd(&g.curL[s], 1)] = r;
}

__global__ void k_l1sort() {
    int s = blockIdx.x * blockDim.x + threadIdx.x;
    if (s >= g.tot[1]) return;
    int n = g.cntL[s];
    if (n < 2) return;
    int* a = g.ordL + g.cstartL[s];
    if (n <= 32) {
        int buf[32];
        for (int i = 0; i < n; i++) buf[i] = a[i];
        for (int i = 1; i < n; i++) {
            int v = buf[i], j = i - 1;
            while (j >= 0 && buf[j] > v) { buf[j + 1] = buf[j]; j--; }
            buf[j + 1] = v;
        }
        for (int i = 0; i < n; i++) a[i] = buf[i];
    } else {
        for (int i = 1; i < n; i++) {
            int v = a[i], j = i - 1;
            while (j >= 0 && a[j] > v) { a[j + 1] = a[j]; j--; }
            a[j + 1] = v;
        }
    }
}

// ------------------------------------------------------------------ levels 2..4 single-block megakernel
template<int GL, int PGb>
__global__ void __launch_bounds__(1024) k_mega(const int* __restrict__ nePrev, int npIdx, int nIdx,
                                               int* __restrict__ rinfo, int* __restrict__ ne,
                                               int* __restrict__ seg, int* __restrict__ ord) {
    constexpr int GS = GL * GL * GL;
    constexpr int GLb = (GL == 16) ? 4 : (GL == 8) ? 3 : 2;
    constexpr int PG = 1 << PGb;
    __shared__ int sA[GS];
    __shared__ int sB[GS];
    __shared__ int mws[32], mwo[32], mtot;
    int tid = threadIdx.x;
    int np = g.tot[npIdx];
    for (int i = tid; i < GS; i += 1024) sA[i] = 0;
    __syncthreads();
    for (int r = tid; r < np; r += 1024) {
        int e = __ldg(nePrev + r);
        int c = ((e & (PG - 1)) >> 1) | ((((e >> PGb) & (PG - 1)) >> 1) << GLb)
              | (((e >> (2 * PGb)) >> 1) << (2 * GLb));
        atomicAdd(&sA[c], 1);
    }
    __syncthreads();
    int i0 = tid * 4;
    int p[4]; int tt = 0;
#pragma unroll
    for (int j = 0; j < 4; j++) {
        int q = 0, idx = i0 + j;
        if (idx < GS) { int cv = sA[idx]; q = cv | ((cv > 0) << 16); }
        p[j] = q; tt += q;
    }
    int inc = wscan(tt);
    if ((tid & 31) == 31) mws[tid >> 5] = inc;
    __syncthreads();
    if (tid == 0) {
        int s = 0;
        for (int w = 0; w < 32; w++) { int x = mws[w]; mwo[w] = s; s += x; }
        mtot = s;
    }
    __syncthreads();
    int exc = mwo[tid >> 5] + inc - tt;
#pragma unroll
    for (int j = 0; j < 4; j++) { int idx = i0 + j; if (idx < GS) sB[idx] = exc; exc += p[j]; }
    if (tid == 0) g.tot[nIdx] = mtot >> 16;
    __syncthreads();
    for (int c = tid; c < GS; c += 1024) {
        int cv = sA[c];
        int rk = sB[c] >> 16;
        rinfo[c] = cv ? rk + 1 : 0;
        if (cv) ne[rk] = c;
    }
    __syncthreads();
    for (int r = tid; r < np; r += 1024) {
        int e = __ldg(nePrev + r);
        int c = ((e & (PG - 1)) >> 1) | ((((e >> PGb) & (PG - 1)) >> 1) << GLb)
              | (((e >> (2 * PGb)) >> 1) << (2 * GLb));
        int v = sB[c];
        seg[r] = v >> 16;
        int old = atomicAdd(&sA[c], 1 << 16);
        ord[(v & 0xffff) + (old >> 16)] = r;
    }
    __syncthreads();
    for (int c = tid; c < GS; c += 1024) {
        int ncnt = sA[c] & 0xffff;
        if (ncnt >= 2) {
            int* a = ord + (sB[c] & 0xffff);
            for (int i = 1; i < ncnt; i++) {
                int vv = a[i], j = i - 1;
                while (j >= 0 && a[j] > vv) { a[j + 1] = a[j]; j--; }
                a[j + 1] = vv;
            }
        }
    }
}

// ------------------------------------------------------------------ edges (all 5 levels, one domain)
__device__ __forceinline__ void edgeDecode(int idx, int& local, int& CGb, const int*& rinfo) {
    if (idx < 7077888)      { local = idx;           CGb = 5; rinfo = g_rinfo0; }
    else if (idx < 7962624) { local = idx - 7077888; CGb = 4; rinfo = g_rinfoL; }
    else if (idx < 8073216) { local = idx - 7962624; CGb = 3; rinfo = g_rinfoL + 32768; }
    else if (idx < 8087040) { local = idx - 8073216; CGb = 2; rinfo = g_rinfoL + 36864; }
    else                    { local = idx - 8087040; CGb = 1; rinfo = g_rinfoL + 37376; }
}

__global__ void k_ecntAll(int* __restrict__ ecnt) {
    int idx = blockIdx.x * 256 + threadIdx.x;
    if (idx >= 8088768) return;
    int local, CGb; const int* rinfo;
    edgeDecode(idx, local, CGb, rinfo);
    int CG = 1 << CGb, FLb = CGb + 1, FL = 1 << FLb, FLsq = 1 << (2 * FLb);
    int a = local & 7, qk = local >> 3;
    int k = qk % 27, q = qk / 27;
    int qx = q & (CG - 1), qy = (q >> CGb) & (CG - 1), qz = q >> (2 * CGb);
    int nx = qx + cNX[k], ny = qy + cNY[k], nz = qz + cNZ[k];
    int c = 0;
    if ((unsigned)nx < (unsigned)CG && (unsigned)ny < (unsigned)CG && (unsigned)nz < (unsigned)CG) {
        int fa = (2 * qx + (a & 1)) + ((2 * qy + ((a >> 1) & 1)) << FLb) + ((2 * qz + (a >> 2)) << (2 * FLb));
        if (__ldg(rinfo + fa)) {
            int m = g.bmask[(k << 3) | a];
            int bb = 2 * nx + (2 * ny << FLb) + (2 * nz << (2 * FLb));
            const int2* rp = (const int2*)rinfo;
            int2 r01 = __ldg(rp + (bb >> 1));
            int2 r23 = __ldg(rp + ((bb + FL) >> 1));
            int2 r45 = __ldg(rp + ((bb + FLsq) >> 1));
            int2 r67 = __ldg(rp + ((bb + FLsq + FL) >> 1));
            c  = ((m >> 0) & 1) & (r01.x != 0);
            c += ((m >> 1) & 1) & (r01.y != 0);
            c += ((m >> 2) & 1) & (r23.x != 0);
            c += ((m >> 3) & 1) & (r23.y != 0);
            c += ((m >> 4) & 1) & (r45.x != 0);
            c += ((m >> 5) & 1) & (r45.y != 0);
            c += ((m >> 6) & 1) & (r67.x != 0);
            c += ((m >> 7) & 1) & (r67.y != 0);
        }
    }
    ecnt[idx] = c;
}

__global__ void k_ewriteAll(const int* __restrict__ eoff, float* __restrict__ out) {
    int idx = blockIdx.x * 256 + threadIdx.x;
    if (idx >= 8088768) return;
    int local, CGb; const int* rinfo;
    edgeDecode(idx, local, CGb, rinfo);
    int CG = 1 << CGb, FLb = CGb + 1, FL = 1 << FLb, FLsq = 1 << (2 * FLb);
    int a = local & 7, qk = local >> 3;
    int k = qk % 27, q = qk / 27;
    int qx = q & (CG - 1), qy = (q >> CGb) & (CG - 1), qz = q >> (2 * CGb);
    int nx = qx + cNX[k], ny = qy + cNY[k], nz = qz + cNZ[k];
    if (!((unsigned)nx < (unsigned)CG && (unsigned)ny < (unsigned)CG && (unsigned)nz < (unsigned)CG))
        return;
    int fa = (2 * qx + (a & 1)) + ((2 * qy + ((a >> 1) & 1)) << FLb) + ((2 * qz + (a >> 2)) << (2 * FLb));
    int ra1 = __ldg(rinfo + fa);
    if (!ra1) return;
    float ra = (float)(ra1 - 1);
    int m = g.bmask[(k << 3) | a];
    int bb = 2 * nx + (2 * ny << FLb) + (2 * nz << (2 * FLb));
    const int2* rp = (const int2*)rinfo;
    int2 r01 = __ldg(rp + (bb >> 1));
    int2 r23 = __ldg(rp + ((bb + FL) >> 1));
    int2 r45 = __ldg(rp + ((bb + FLsq) >> 1));
    int2 r67 = __ldg(rp + ((bb + FLsq + FL) >> 1));
    int rv[8] = {r01.x, r01.y, r23.x, r23.y, r45.x, r45.y, r67.x, r67.y};
    int E = g.E;
    float* o0 = out + g.oedge + __ldg(eoff + idx);
#pragma unroll
    for (int b = 0; b < 8; b++) {
        if (((m >> b) & 1) && rv[b]) {
            o0[0] = (float)(rv[b] - 1);
            o0[E] = ra;
            o0++;
        }
    }
}

// ------------------------------------------------------------------ sv
__global__ void k_sv0(const float* __restrict__ nodes) {
    int i = blockIdx.x * blockDim.x + threadIdx.x;
    if (i >= NPT) return;
    int s = g.seg0[i];
    float m = nodes[i * 10];
    float* row = g.svraw + (size_t)s * 10;
    atomicAdd(row, m);
#pragma unroll
    for (int j = 1; j < 10; j++)
        atomicAdd(row + j, m * nodes[i * 10 + j]);
}

__global__ void k_svagg(int soffP, int soffC, const int* __restrict__ seg, int npIdx) {
    int r = blockIdx.x * blockDim.x + threadIdx.x;
    if (r >= g.tot[npIdx]) return;
    const float* pr = g.svraw + (size_t)(soffP + r) * 10;
    float* row = g.svraw + (size_t)(soffC + seg[r]) * 10;
#pragma unroll
    for (int j = 0; j < 10; j++)
        atomicAdd(row + j, pr[j]);
}

// ------------------------------------------------------------------ layout + writers
__global__ void k_off() {
    int n0 = g.tot[0], n1 = g.tot[1], n2 = g.tot[2], n3 = g.tot[3], n4 = g.tot[4];
    int T = g.tot[5], E = g.tot[6];
    int A = NPT + n0 + n1 + n2 + n3;
    int S = n0 + n1 + n2 + n3 + n4;
    g.A = A; g.S = S; g.E = E;
    g.oassign = 2 * T;
    g.osv = 2 * T + 2 * A;
    g.oedge = g.osv + 10 * S;
    g.oids = g.oedge + 2 * E;
    g.svb[0] = 0; g.svb[1] = n0; g.svb[2] = n0 + n1; g.svb[3] = n0 + n1 + n2; g.svb[4] = n0 + n1 + n2 + n3;
    g.ab[0] = 0; g.ab[1] = NPT; g.ab[2] = NPT + n0; g.ab[3] = NPT + n0 + n1; g.ab[4] = NPT + n0 + n1 + n2;
}

__global__ void k_awriteAll(float* __restrict__ out) {
    int t = blockIdx.x * blockDim.x + threadIdx.x;
    if (t >= g.A) return;
    const int* ord; const int* seg; int loc;
    if (t < g.ab[1])      { ord = g.order0;          seg = g.seg0;            loc = t; }
    else if (t < g.ab[2]) { ord = g.ordL + 0;        seg = g.segL + 0;        loc = t - g.ab[1]; }
    else if (t < g.ab[3]) { ord = g.ordL + 262144;   seg = g.segL + 262144;   loc = t - g.ab[2]; }
    else if (t < g.ab[4]) { ord = g.ordL + 294912;   seg = g.segL + 294912;   loc = t - g.ab[3]; }
    else                  { ord = g.ordL + 299008;   seg = g.segL + 299008;   loc = t - g.ab[4]; }
    int p = ord[loc];
    out[g.oassign + t] = (float)seg[p];
    out[g.oassign + g.A + t] = (float)p;
}

__global__ void k_svidwrite(float* __restrict__ out) {
    int r = blockIdx.x * blockDim.x + threadIdx.x;
    if (r >= g.S) return;
    int neo;
    if (r < g.svb[1])      neo = 0;
    else if (r < g.svb[2]) neo = 262144 - g.svb[1];
    else if (r < g.svb[3]) neo = 294912 - g.svb[2];
    else if (r < g.svb[4]) neo = 299008 - g.svb[3];
    else                   neo = 299520 - g.svb[4];
    int loc = neo + r;
    out[g.oids + r] = (float)g.neA[loc];
    const float* raw = g.svraw + (size_t)loc * 10;
    float m = raw[0];
    float* o = out + g.osv + (size_t)r * 10;
    o[0] = m;
#pragma unroll
    for (int j = 1; j < 10; j++) o[j] = raw[j] / m;
}

// ------------------------------------------------------------------ host
extern "C" void kernel_launch(void* const* d_in, const int* in_sizes, int n_in,
                              void* d_out, int out_size) {
    const float* nodes = (const float*)d_in[0];
    float* out = (float*)d_out;
    GG* G;
    cudaGetSymbolAddress((void**)&G, g);
    int *rinfoL, *ecnt8, *eoff8;
    cudaGetSymbolAddress((void**)&rinfoL, g_rinfoL);
    cudaGetSymbolAddress((void**)&ecnt8, g_ecnt8);
    cudaGetSymbolAddress((void**)&eoff8, g_eoff8);

    cudaMemsetAsync(G, 0, offsetof(GG, zend), 0);
    k_init2<<<1, 256>>>();
    k_foldpre<<<768, 256>>>(nodes);
    k_mmx<<<16, 256>>>(nodes);
    k_fold3b<<<1, 128>>>(nodes);
    k_cells<<<NPT / 256, 256>>>(nodes);
    k_scan2<<<32, 512>>>(G->occ0, G->cnt0, G->rank0, G->cstart0, C0, &G->tot[0], 0, 0);
    k_post0<<<C0 / 256, 256>>>();
    // per-cell degree via separable box filter (temporaries in edge buffers, free until edge phase)
    k_conv<<<1024, 256>>>(G->cnt0, ecnt8, 0);
    k_conv<<<1024, 256>>>(ecnt8, eoff8, 6);
    k_conv<<<1024, 256>>>(eoff8, ecnt8, 12);
    k_scatseg<<<NPT / 256, 256>>>(ecnt8);
    k_sort0<<<C0 / 256, 256>>>();
    k_scan1<<<32, 512>>>(G->pdeg, G->poff, NPT, &G->tot[5], 1, 32);

    // level 1
    k_l1occup<<<NPT / 256, 256>>>();
    k_scan1<<<4, 512>>>(G->occL, G->rankL, 32768, &G->tot[1], 2, 64);
    k_l1post<<<32768 / 256, 256>>>();
    k_l1seg<<<NPT / 256, 256>>>();
    k_scan1<<<4, 512>>>(G->cntL, G->cstartL, 32768, nullptr, 3, 68);
    k_l1scat<<<NPT / 256, 256>>>();
    k_l1sort<<<32768 / 256, 256>>>();

    // levels 2..4 (single-block megakernels)
    k_mega<16, 5><<<1, 1024>>>(G->neA + 262144, 1, 2, rinfoL + 32768, G->neA + 294912,
                               G->segL + 262144, G->ordL + 262144);
    k_mega<8, 4><<<1, 1024>>>(G->neA + 294912, 2, 3, rinfoL + 36864, G->neA + 299008,
                              G->segL + 294912, G->ordL + 294912);
    k_mega<4, 3><<<1, 1024>>>(G->neA + 299008, 3, 4, rinfoL + 37376, G->neA + 299520,
                              G->segL + 299008, G->ordL + 299008);

    // edges: one count kernel + one scan + one writer
    k_ecntAll<<<(8088768 + 255) / 256, 256>>>(ecnt8);
    k_scan1<<<(8088768 + 8191) / 8192, 512>>>(ecnt8, eoff8, 8088768, &G->tot[6], 4, 72);

    k_off<<<1, 1>>>();

    // supervoxel features (raw sums; normalize at output)
    k_sv0<<<NPT / 256, 256>>>(nodes);
    k_svagg<<<NPT / 256, 256>>>(0, 262144, G->segL + 0, 0);
    k_svagg<<<(262144 + 255) / 256, 256>>>(262144, 294912, G->segL + 262144, 1);
    k_svagg<<<(32768 + 255) / 256, 256>>>(294912, 299008, G->segL + 294912, 2);
    k_svagg<<<(4096 + 255) / 256, 256>>>(299008, 299520, G->segL + 299008, 3);

    // writers
    k_gwrite<<<NPT / 256, 256>>>(out);
    k_awriteAll<<<(NPT + 299520 + 255) / 256, 256>>>(out);
    k_svidwrite<<<(299584 + 255) / 256, 256>>>(out);
    k_ewriteAll<<<(8088768 + 255) / 256, 256>>>(eoff8, out);
    (void)in_sizes; (void)n_in; (void)out_size;
}